// round 6
// baseline (speedup 1.0000x reference)
#include <cuda_runtime.h>
#include <math.h>

#define B_DIM 128
#define TDIM 8192
#define NFEAT 32
#define MS 16
#define NEAR_END 6553       // int(8192*0.8); mask is P > NEAR_END

// ---- device scratch --------------------------------------------------------
__device__ float  g_mean[B_DIM * TDIM];   // 4 MB per-timestep means
__device__ float4 g_tabL[TDIM];           // (1/fL, 1/(fL-1), 1/aL, fL)     zero for invalid P
__device__ float4 g_tabR[TDIM];           // (1/fR, 1/(fR-1), 1/aR, logC)   zero for invalid P

// ============================================================================
// Kernel A: feature-mean streaming reduction + per-P constant tables.
// 8 independent 512B warp-loads in flight per iteration.
// ============================================================================
#define MEAN_GRID 2048
#define MEAN_NT   256
#define TOTAL_T4  (B_DIM * TDIM / 4)         // 262144
#define NWARPS    (MEAN_GRID * MEAN_NT / 32) // 16384
#define UNROLL    8

__global__ __launch_bounds__(MEAN_NT)
void mean_kernel(const float4* __restrict__ x4,
                 const float* __restrict__ prior_var,
                 const float* __restrict__ noise_var)
{
    const int lane = threadIdx.x & 31;
    const int wg   = (blockIdx.x * MEAN_NT + threadIdx.x) >> 5;

    // ---- per-P constant tables (first 8192 threads; ALU hidden under streaming)
    const int gtid = blockIdx.x * MEAN_NT + threadIdx.x;
    if (gtid >= MS && gtid < TDIM - MS) {
        const float pv = log1pf(expf(prior_var[0]));
        const float nv = log1pf(expf(noise_var[0]));
        const float inv_pv = 1.0f / pv;
        const float inv_nv = 1.0f / nv;
        const float fL = (float)gtid;
        const float fR = (float)(TDIM - gtid);
        const float aL = inv_pv + fL * inv_nv;
        const float aR = inv_pv + fR * inv_nv;
        const float aW = inv_pv + (float)TDIM * inv_nv;
        const float logC = -0.5f * logf((pv / aW) * aL * aR);
        g_tabL[gtid] = make_float4(1.0f / fL, 1.0f / (fL - 1.0f), 1.0f / aL, fL);
        g_tabR[gtid] = make_float4(1.0f / fR, 1.0f / (fR - 1.0f), 1.0f / aR, logC);
    }

    // ---- streaming mean reduction --------------------------------------------
    #pragma unroll
    for (int it = 0; it < TOTAL_T4 / (UNROLL * NWARPS); ++it) {
        const int t4_0 = wg + it * UNROLL * NWARPS;
        float s[UNROLL];
        float4 v[UNROLL];
        #pragma unroll
        for (int k = 0; k < UNROLL; ++k)
            v[k] = __ldcs(&x4[(size_t)(t4_0 + k * NWARPS) * 32 + lane]);
        #pragma unroll
        for (int k = 0; k < UNROLL; ++k)
            s[k] = (v[k].x + v[k].y) + (v[k].z + v[k].w);
        #pragma unroll
        for (int d = 1; d < 8; d <<= 1) {
            #pragma unroll
            for (int k = 0; k < UNROLL; ++k)
                s[k] += __shfl_xor_sync(0xffffffffu, s[k], d);
        }
        if ((lane & 7) == 0) {
            const int r = lane >> 3;
            #pragma unroll
            for (int k = 0; k < UNROLL; ++k)
                g_mean[(t4_0 + k * NWARPS) * 4 + r] = s[k] * (1.0f / NFEAT);
        }
    }
}

// ============================================================================
// Kernel B: per-row prefix scan + table-driven Bayes factor + softmax.
// ============================================================================
#define NT 1024
#define CHUNK (TDIM / NT)   // 8

__global__ __launch_bounds__(NT, 1)
void score_kernel(const float* __restrict__ prior_mean,
                  const float* __restrict__ prior_var,
                  const float* __restrict__ noise_var,
                  float* __restrict__ out)
{
    __shared__ float ws1[32], ws2[32];
    __shared__ float rwarp[32], rwarp2[32];
    __shared__ float bcast[1];

    const int b    = blockIdx.x;
    const int tid  = threadIdx.x;
    const int lane = tid & 31;
    const int warp = tid >> 5;
    const int base = tid * CHUNK;

    // ---- load this thread's 8 means + chunk sums ------------------------------
    float loc[CHUNK];
    const float4* mrow = reinterpret_cast<const float4*>(g_mean + (size_t)b * TDIM);
    float c1 = 0.f, c2 = 0.f;
    #pragma unroll
    for (int q = 0; q < CHUNK / 4; ++q) {
        float4 v = mrow[tid * (CHUNK / 4) + q];
        loc[q * 4 + 0] = v.x; loc[q * 4 + 1] = v.y;
        loc[q * 4 + 2] = v.z; loc[q * 4 + 3] = v.w;
        c1 += (v.x + v.y) + (v.z + v.w);
        c2 += (v.x * v.x + v.y * v.y) + (v.z * v.z + v.w * v.w);
    }

    // ---- block prefix scan of chunk sums (m, m^2) -----------------------------
    float i1 = c1, i2 = c2;
    #pragma unroll
    for (int d = 1; d < 32; d <<= 1) {
        float a = __shfl_up_sync(0xffffffffu, i1, d);
        float bb = __shfl_up_sync(0xffffffffu, i2, d);
        if (lane >= d) { i1 += a; i2 += bb; }
    }
    if (lane == 31) { ws1[warp] = i1; ws2[warp] = i2; }
    __syncthreads();
    if (warp == 0) {
        float a1 = ws1[lane];
        float a2 = ws2[lane];
        #pragma unroll
        for (int d = 1; d < 32; d <<= 1) {
            float u = __shfl_up_sync(0xffffffffu, a1, d);
            float v = __shfl_up_sync(0xffffffffu, a2, d);
            if (lane >= d) { a1 += u; a2 += v; }
        }
        ws1[lane] = a1; ws2[lane] = a2;
    }
    __syncthreads();
    const float off1 = (warp > 0) ? ws1[warp - 1] : 0.f;
    const float off2 = (warp > 0) ? ws2[warp - 1] : 0.f;
    float cs1 = off1 + (i1 - c1);   // exclusive prefix at chunk start
    float cs2 = off2 + (i2 - c2);
    const float totS = ws1[31];
    const float totQ = ws2[31];

    // ---- row constants --------------------------------------------------------
    const float pm = prior_mean[0];
    const float pv = log1pf(expf(prior_var[0]));
    const float nv = log1pf(expf(noise_var[0]));
    const float inv_pv = 1.0f / pv;
    const float inv_nv = 1.0f / nv;
    const float pmipv  = pm * inv_pv;
    const float pm2pv  = pm * pm * inv_pv;

    const float nW = (float)TDIM;
    const float aW = inv_pv + nW * inv_nv;
    const float rcp_aW = 1.0f / aW;
    const float btW = pmipv + totS * inv_nv;
    const float s2nW = totS * totS / nW;
    const float vW = fmaxf((totQ - s2nW) / (nW - 1.0f), 1e-8f);
    const float K = 0.5f * ((nW * vW + s2nW) * inv_nv - btW * btW * rcp_aW - pm2pv);
    const float nhalf_inv_nv = -0.5f * inv_nv;

    // ---- per-P Bayes factor (table-driven, branchless) ------------------------
    #pragma unroll
    for (int j = 0; j < CHUNK; ++j) {
        const int P = base + j;
        const float mv = loc[j];
        const bool valid = (P >= MS) && (P < TDIM - MS);

        const float4 tL = g_tabL[P];   // (1/fL, 1/(fL-1), 1/aL, fL)
        const float4 tR = g_tabR[P];   // (1/fR, 1/(fR-1), 1/aR, logC)

        const float sL = cs1, qL = cs2;
        const float sR = totS - sL, qR = totQ - qL;

        const float s2L = sL * sL * tL.x;
        const float vL  = fmaxf((qL - s2L) * tL.y, 1e-8f);
        const float s2R = sR * sR * tR.x;
        const float vR  = fmaxf((qR - s2R) * tR.y, 1e-8f);

        const float fL = tL.w;
        const float fR = nW - fL;
        const float sumv = (fL * vL + s2L) + (fR * vR + s2R);

        const float btL = pmipv + sL * inv_nv;
        const float btR = pmipv + sR * inv_nv;
        const float quad = btL * btL * tL.z + btR * btR * tR.z;

        const float bf = tR.w + fmaf(nhalf_inv_nv, sumv, 0.5f * quad) + K;
        loc[j] = valid ? bf : -INFINITY;

        cs1 += mv;
        cs2 += mv * mv;
    }

    // ---- reductions: max, then (sum, masked sum) ------------------------------
    float vmax = -INFINITY;
    #pragma unroll
    for (int j = 0; j < CHUNK; ++j) vmax = fmaxf(vmax, loc[j]);
    #pragma unroll
    for (int d = 16; d > 0; d >>= 1)
        vmax = fmaxf(vmax, __shfl_xor_sync(0xffffffffu, vmax, d));
    if (lane == 0) rwarp[warp] = vmax;
    __syncthreads();
    if (warp == 0) {
        float m = rwarp[lane];
        #pragma unroll
        for (int d = 16; d > 0; d >>= 1)
            m = fmaxf(m, __shfl_xor_sync(0xffffffffu, m, d));
        if (lane == 0) bcast[0] = m;
    }
    __syncthreads();
    const float bfmax = bcast[0];

    float s_all = 0.f, s_msk = 0.f;
    #pragma unroll
    for (int j = 0; j < CHUNK; ++j) {
        const int P = base + j;
        const float e = __expf(loc[j] - bfmax);   // exp(-inf)=0 for invalid P
        s_all += e;
        if (P > NEAR_END) s_msk += e;
    }
    #pragma unroll
    for (int d = 16; d > 0; d >>= 1) {
        s_all += __shfl_xor_sync(0xffffffffu, s_all, d);
        s_msk += __shfl_xor_sync(0xffffffffu, s_msk, d);
    }
    if (lane == 0) { rwarp[warp] = s_all; rwarp2[warp] = s_msk; }
    __syncthreads();
    if (warp == 0) {
        float a = rwarp[lane];
        float m = rwarp2[lane];
        #pragma unroll
        for (int d = 16; d > 0; d >>= 1) {
            a += __shfl_xor_sync(0xffffffffu, a, d);
            m += __shfl_xor_sync(0xffffffffu, m, d);
        }
        if (lane == 0) {
            const float weight = m / a;
            const float conf = 1.0f / (1.0f + __expf(-bfmax));
            out[b] = conf * weight;
        }
    }
}

extern "C" void kernel_launch(void* const* d_in, const int* in_sizes, int n_in,
                              void* d_out, int out_size)
{
    const float4* x4 = (const float4*)d_in[0];
    const float* pm = (const float*)d_in[1];
    const float* pv = (const float*)d_in[2];
    const float* nv = (const float*)d_in[3];
    float* out = (float*)d_out;
    mean_kernel<<<MEAN_GRID, MEAN_NT>>>(x4, pv, nv);
    score_kernel<<<out_size, NT>>>(pm, pv, nv, out);
}

// round 7
// speedup vs baseline: 1.1914x; 1.1914x over previous
#include <cuda_runtime.h>
#include <math.h>

#define B_DIM 128
#define TDIM 8192
#define NFEAT 32
#define MS 16
#define NEAR_END 6553       // int(8192*0.8); mask is P > NEAR_END

// ---- device scratch --------------------------------------------------------
__device__ float g_mean[B_DIM * TDIM];   // 4 MB per-timestep means
__device__ float g_logc[TDIM];           // -0.5*log(pv*aL*aR/aW); zero for invalid P

// ============================================================================
// Kernel A: feature-mean streaming reduction + per-P log table.
// 8 independent 512B warp-loads in flight per iteration.
// ============================================================================
#define MEAN_GRID 2048
#define MEAN_NT   256
#define TOTAL_T4  (B_DIM * TDIM / 4)         // 262144
#define NWARPS    (MEAN_GRID * MEAN_NT / 32) // 16384
#define UNROLL    8

__global__ __launch_bounds__(MEAN_NT)
void mean_kernel(const float4* __restrict__ x4,
                 const float* __restrict__ prior_var,
                 const float* __restrict__ noise_var)
{
    const int lane = threadIdx.x & 31;
    const int wg   = (blockIdx.x * MEAN_NT + threadIdx.x) >> 5;

    // ---- per-P log table (first 8192 threads; hidden under streaming) --------
    const int gtid = blockIdx.x * MEAN_NT + threadIdx.x;
    if (gtid >= MS && gtid < TDIM - MS) {
        const float pv = log1pf(expf(prior_var[0]));
        const float nv = log1pf(expf(noise_var[0]));
        const float inv_pv = 1.0f / pv;
        const float inv_nv = 1.0f / nv;
        const float fL = (float)gtid;
        const float fR = (float)(TDIM - gtid);
        const float aL = inv_pv + fL * inv_nv;
        const float aR = inv_pv + fR * inv_nv;
        const float aW = inv_pv + (float)TDIM * inv_nv;
        g_logc[gtid] = -0.5f * logf((pv / aW) * aL * aR);
    }

    // ---- streaming mean reduction --------------------------------------------
    #pragma unroll
    for (int it = 0; it < TOTAL_T4 / (UNROLL * NWARPS); ++it) {
        const int t4_0 = wg + it * UNROLL * NWARPS;
        float s[UNROLL];
        float4 v[UNROLL];
        #pragma unroll
        for (int k = 0; k < UNROLL; ++k)
            v[k] = __ldcs(&x4[(size_t)(t4_0 + k * NWARPS) * 32 + lane]);
        #pragma unroll
        for (int k = 0; k < UNROLL; ++k)
            s[k] = (v[k].x + v[k].y) + (v[k].z + v[k].w);
        #pragma unroll
        for (int d = 1; d < 8; d <<= 1) {
            #pragma unroll
            for (int k = 0; k < UNROLL; ++k)
                s[k] += __shfl_xor_sync(0xffffffffu, s[k], d);
        }
        if ((lane & 7) == 0) {
            const int r = lane >> 3;
            #pragma unroll
            for (int k = 0; k < UNROLL; ++k)
                g_mean[(t4_0 + k * NWARPS) * 4 + r] = s[k] * (1.0f / NFEAT);
        }
    }
}

// ============================================================================
// Kernel B: per-row prefix scan + Bayes factor + softmax.
// SMEM-staged coalesced loads; log table from SMEM; 3 MUFU per P.
// ============================================================================
#define NT 1024
#define CHUNK (TDIM / NT)   // 8

__global__ __launch_bounds__(NT, 1)
void score_kernel(const float* __restrict__ prior_mean,
                  const float* __restrict__ prior_var,
                  const float* __restrict__ noise_var,
                  float* __restrict__ out)
{
    __shared__ float4 sbuf[TDIM / 4];     // 32 KB staging: means, then logC
    __shared__ float ws1[32], ws2[32];
    __shared__ float rwarp[32], rwarp2[32];
    __shared__ float bcast[1];

    const int b    = blockIdx.x;
    const int tid  = threadIdx.x;
    const int lane = tid & 31;
    const int warp = tid >> 5;
    const int base = tid * CHUNK;

    // ---- stage means through SMEM (coalesced GMEM, blocked SMEM reads) --------
    const float4* mrow4 = reinterpret_cast<const float4*>(g_mean + (size_t)b * TDIM);
    sbuf[tid]        = mrow4[tid];
    sbuf[tid + 1024] = mrow4[tid + 1024];
    __syncthreads();

    float loc[CHUNK];
    float c1 = 0.f, c2 = 0.f;
    #pragma unroll
    for (int q = 0; q < CHUNK / 4; ++q) {
        float4 v = sbuf[tid * (CHUNK / 4) + q];
        loc[q * 4 + 0] = v.x; loc[q * 4 + 1] = v.y;
        loc[q * 4 + 2] = v.z; loc[q * 4 + 3] = v.w;
        c1 += (v.x + v.y) + (v.z + v.w);
        c2 += (v.x * v.x + v.y * v.y) + (v.z * v.z + v.w * v.w);
    }

    // ---- block prefix scan of chunk sums (m, m^2) -----------------------------
    float i1 = c1, i2 = c2;
    #pragma unroll
    for (int d = 1; d < 32; d <<= 1) {
        float a = __shfl_up_sync(0xffffffffu, i1, d);
        float bb = __shfl_up_sync(0xffffffffu, i2, d);
        if (lane >= d) { i1 += a; i2 += bb; }
    }
    if (lane == 31) { ws1[warp] = i1; ws2[warp] = i2; }
    __syncthreads();          // also: all step-2 sbuf reads are done past here
    if (warp == 0) {
        float a1 = ws1[lane];
        float a2 = ws2[lane];
        #pragma unroll
        for (int d = 1; d < 32; d <<= 1) {
            float u = __shfl_up_sync(0xffffffffu, a1, d);
            float v = __shfl_up_sync(0xffffffffu, a2, d);
            if (lane >= d) { a1 += u; a2 += v; }
        }
        ws1[lane] = a1; ws2[lane] = a2;
    }
    __syncthreads();
    const float off1 = (warp > 0) ? ws1[warp - 1] : 0.f;
    const float off2 = (warp > 0) ? ws2[warp - 1] : 0.f;
    float cs1 = off1 + (i1 - c1);   // exclusive prefix at chunk start
    float cs2 = off2 + (i2 - c2);
    const float totS = ws1[31];
    const float totQ = ws2[31];

    // ---- overwrite staging buffer with logC table (coalesced) -----------------
    const float4* lrow4 = reinterpret_cast<const float4*>(g_logc);
    sbuf[tid]        = lrow4[tid];
    sbuf[tid + 1024] = lrow4[tid + 1024];

    // ---- row constants --------------------------------------------------------
    const float pm = prior_mean[0];
    const float pv = log1pf(expf(prior_var[0]));
    const float nv = log1pf(expf(noise_var[0]));
    const float inv_pv = 1.0f / pv;
    const float inv_nv = 1.0f / nv;
    const float pmipv  = pm * inv_pv;
    const float pm2pv  = pm * pm * inv_pv;

    const float nW = (float)TDIM;
    const float aW = inv_pv + nW * inv_nv;
    const float rcp_aW = 1.0f / aW;
    const float btW = pmipv + totS * inv_nv;
    const float s2nW = totS * totS / nW;
    const float vW = fmaxf((totQ - s2nW) / (nW - 1.0f), 1e-8f);
    const float K = 0.5f * ((nW * vW + s2nW) * inv_nv - btW * btW * rcp_aW - pm2pv);
    const float nhalf_inv_nv = -0.5f * inv_nv;

    __syncthreads();   // logC staged

    float lc[CHUNK];
    #pragma unroll
    for (int q = 0; q < CHUNK / 4; ++q) {
        float4 v = sbuf[tid * (CHUNK / 4) + q];
        lc[q * 4 + 0] = v.x; lc[q * 4 + 1] = v.y;
        lc[q * 4 + 2] = v.z; lc[q * 4 + 3] = v.w;
    }

    // ---- per-P Bayes factor (3 MUFU per P, no log) ----------------------------
    const float base_f = (float)base;
    #pragma unroll
    for (int j = 0; j < CHUNK; ++j) {
        const int P = base + j;
        const float mv = loc[j];
        const bool valid = (P >= MS) && (P < TDIM - MS);

        const float fL = base_f + (float)j;
        const float fR = nW - fL;

        // fused reciprocals: 1/fL and 1/(fL-1) from one RCP
        const float rLL = __fdividef(1.0f, fL * (fL - 1.0f));
        const float rL   = rLL * (fL - 1.0f);
        const float rLm1 = rLL * fL;
        const float rRR = __fdividef(1.0f, fR * (fR - 1.0f));
        const float rR   = rRR * (fR - 1.0f);
        const float rRm1 = rRR * fR;

        const float sL = cs1, qL = cs2;
        const float sR = totS - sL, qR = totQ - qL;

        const float s2L = sL * sL * rL;
        const float vL  = fmaxf((qL - s2L) * rLm1, 1e-8f);
        const float s2R = sR * sR * rR;
        const float vR  = fmaxf((qR - s2R) * rRm1, 1e-8f);
        const float sumv = (fL * vL + s2L) + (fR * vR + s2R);

        const float aL = inv_pv + fL * inv_nv;
        const float aR = inv_pv + fR * inv_nv;
        const float btL = pmipv + sL * inv_nv;
        const float btR = pmipv + sR * inv_nv;
        // btL^2/aL + btR^2/aR with a single reciprocal
        const float rprod = __fdividef(1.0f, aL * aR);
        const float quad = (btL * btL * aR + btR * btR * aL) * rprod;

        const float bf = lc[j] + fmaf(nhalf_inv_nv, sumv, 0.5f * quad) + K;
        loc[j] = valid ? bf : -INFINITY;

        cs1 += mv;
        cs2 += mv * mv;
    }

    // ---- reductions: max, then (sum, masked sum) ------------------------------
    float vmax = -INFINITY;
    #pragma unroll
    for (int j = 0; j < CHUNK; ++j) vmax = fmaxf(vmax, loc[j]);
    #pragma unroll
    for (int d = 16; d > 0; d >>= 1)
        vmax = fmaxf(vmax, __shfl_xor_sync(0xffffffffu, vmax, d));
    if (lane == 0) rwarp[warp] = vmax;
    __syncthreads();
    if (warp == 0) {
        float m = rwarp[lane];
        #pragma unroll
        for (int d = 16; d > 0; d >>= 1)
            m = fmaxf(m, __shfl_xor_sync(0xffffffffu, m, d));
        if (lane == 0) bcast[0] = m;
    }
    __syncthreads();
    const float bfmax = bcast[0];

    float s_all = 0.f, s_msk = 0.f;
    #pragma unroll
    for (int j = 0; j < CHUNK; ++j) {
        const int P = base + j;
        const float e = __expf(loc[j] - bfmax);   // exp(-inf)=0 for invalid P
        s_all += e;
        if (P > NEAR_END) s_msk += e;
    }
    #pragma unroll
    for (int d = 16; d > 0; d >>= 1) {
        s_all += __shfl_xor_sync(0xffffffffu, s_all, d);
        s_msk += __shfl_xor_sync(0xffffffffu, s_msk, d);
    }
    if (lane == 0) { rwarp[warp] = s_all; rwarp2[warp] = s_msk; }
    __syncthreads();
    if (warp == 0) {
        float a = rwarp[lane];
        float m = rwarp2[lane];
        #pragma unroll
        for (int d = 16; d > 0; d >>= 1) {
            a += __shfl_xor_sync(0xffffffffu, a, d);
            m += __shfl_xor_sync(0xffffffffu, m, d);
        }
        if (lane == 0) {
            const float weight = m / a;
            const float conf = 1.0f / (1.0f + __expf(-bfmax));
            out[b] = conf * weight;
        }
    }
}

extern "C" void kernel_launch(void* const* d_in, const int* in_sizes, int n_in,
                              void* d_out, int out_size)
{
    const float4* x4 = (const float4*)d_in[0];
    const float* pm = (const float*)d_in[1];
    const float* pv = (const float*)d_in[2];
    const float* nv = (const float*)d_in[3];
    float* out = (float*)d_out;
    mean_kernel<<<MEAN_GRID, MEAN_NT>>>(x4, pv, nv);
    score_kernel<<<out_size, NT>>>(pm, pv, nv, out);
}